// round 15
// baseline (speedup 1.0000x reference)
#include <cuda_runtime.h>
#include <cuda_bf16.h>
#include <math.h>
#include <stdint.h>

// ---------------- problem dims ----------------
#define Bn   256
#define Ln   512
#define Cn   32
#define NBn  4
#define SEGn 64
#define FREQn 8
#define STEPn 4
#define Dn   512
#define Hn   1024
#define FINn 2048
#define Fn   257

// ---------------- scratch ----------------
__device__ float g_mean [Bn*Cn];
__device__ float g_std  [Bn*Cn];
__device__ float g_cf   [NBn*Fn];
__device__ float g_rho  [NBn*Ln];
__device__ float g_T    [(size_t)NBn*Ln*Ln];
__device__ float g_encx [(size_t)NBn*Bn*FREQn*Dn];
__device__ float g_dec2 [(size_t)NBn*Bn*STEPn*FINn];
__device__ float g_bfuse[NBn*Dn];

#define BDECL(name, n) __device__ __align__(16) __nv_bfloat16 name##h[(size_t)(n)], name##l[(size_t)(n)]
BDECL(g_T16,  NBn*Ln*Ln);
BDECL(g_xnT,  Bn*Cn*Ln);
BDECL(g_xi,   (size_t)NBn*Bn*Ln*Cn);
BDECL(g_enc1, (size_t)NBn*Bn*FREQn*Hn);
BDECL(g_encx16, (size_t)NBn*Bn*FREQn*Dn);
BDECL(g_hA,   NBn*Bn*Dn);
BDECL(g_hB,   NBn*Bn*Dn);
BDECL(g_preds, NBn*Bn*STEPn*Dn);
BDECL(g_dec1, (size_t)NBn*Bn*STEPn*Hn);
BDECL(g_ew1,  (size_t)NBn*Hn*FINn);
BDECL(g_ew2T, (size_t)NBn*Hn*Dn);
BDECL(g_wf,   (size_t)NBn*Dn*Hn);
BDECL(g_wxh,  NBn*Dn*Dn);
BDECL(g_whh,  NBn*Dn*Dn);
BDECL(g_dw1,  (size_t)NBn*Hn*Dn);
BDECL(g_dw2,  (size_t)NBn*FINn*Hn);

// ---------------- prep kernels ----------------
__global__ void cf_k(const float* __restrict__ mw) {
    int i = blockIdx.x * 256 + threadIdx.x;
    if (i < NBn * Fn) g_cf[i] = 1.f / (1.f + expf(-mw[i]));
}
__global__ void rho_k() {
    int nb = blockIdx.x, d = threadIdx.x;
    const float* cf = g_cf + nb * Fn;
    const float ST = 6.28318530717958647692f / 512.f;
    float s = cf[0] + ((d & 1) ? -cf[256] : cf[256]);
    for (int k = 1; k <= 255; k++)
        s += 2.f * cf[k] * cosf((float)((k * d) & 511) * ST);
    g_rho[nb * Ln + d] = s * (1.f / 512.f);
}
__global__ void tbuild_k() {
    int i = blockIdx.x * 256 + threadIdx.x;
    int nb = i >> 18, t = (i >> 9) & 511, tp = i & 511;
    g_T[i] = g_rho[nb * Ln + ((t - tp) & 511)];
}
__global__ void split_k(const float* __restrict__ s, __nv_bfloat16* __restrict__ h,
                        __nv_bfloat16* __restrict__ l, int n) {
    int i = blockIdx.x * 256 + threadIdx.x;
    if (i >= n) return;
    float v = s[i];
    __nv_bfloat16 hh = __float2bfloat16(v);
    h[i] = hh;
    l[i] = __float2bfloat16(v - __bfloat162float(hh));
}
// transpose + split: src [z][R][Cc] fp32 -> out [z][Cc][R] bf16 hi/lo (32x32 tiles, 256 thr)
__global__ void tsplit_k(const float* __restrict__ src, __nv_bfloat16* __restrict__ th,
                         __nv_bfloat16* __restrict__ tl, int R, int Cc) {
    __shared__ float t[32][33];
    int z = blockIdx.z;
    int r0 = blockIdx.y * 32, c0 = blockIdx.x * 32;
    int tx = threadIdx.x & 31, ty = threadIdx.x >> 5;
    const float* s = src + (size_t)z * R * Cc;
    #pragma unroll
    for (int j = 0; j < 32; j += 8)
        t[ty + j][tx] = s[(size_t)(r0 + ty + j) * Cc + c0 + tx];
    __syncthreads();
    __nv_bfloat16* oh = th + (size_t)z * R * Cc;
    __nv_bfloat16* ol = tl + (size_t)z * R * Cc;
    #pragma unroll
    for (int j = 0; j < 32; j += 8) {
        float v = t[tx][ty + j];
        __nv_bfloat16 h = __float2bfloat16(v);
        size_t o = (size_t)(c0 + ty + j) * R + r0 + tx;
        oh[o] = h;
        ol[o] = __float2bfloat16(v - __bfloat162float(h));
    }
}
// bfuse[nb][d] = sum_k wxh[nb][d][k] * eb2[nb][k]
__global__ void bfuse_k(const float* __restrict__ wxh, const float* __restrict__ eb2) {
    int i = blockIdx.x * 256 + threadIdx.x;
    if (i >= NBn * Dn) return;
    int nb = i >> 9;
    const float* w = wxh + (size_t)i * Dn;
    const float* b = eb2 + nb * Dn;
    float s = 0.f;
    for (int k = 0; k < Dn; k++) s = fmaf(w[k], b[k], s);
    g_bfuse[i] = s;
}

// ---------------- instance norm + transposed split-bf16 write ----------------
__global__ void instnorm_k(const float* __restrict__ x) {
    int b = blockIdx.x;
    int c = threadIdx.x & 31, r = threadIdx.x >> 5;
    const float* xb = x + (size_t)b * Ln * Cn;
    float s = 0.f, sq = 0.f;
    for (int t = r; t < Ln; t += 8) { float v = xb[t * Cn + c]; s += v; sq += v * v; }
    __shared__ float ss[8][32], sg[8][32], smean[32], srstd[32];
    ss[r][c] = s; sg[r][c] = sq;
    __syncthreads();
    if (threadIdx.x < 32) {
        float a = 0.f, q = 0.f;
        #pragma unroll
        for (int j = 0; j < 8; j++) { a += ss[j][threadIdx.x]; q += sg[j][threadIdx.x]; }
        float m = a * (1.f / 512.f);
        float var = q * (1.f / 512.f) - m * m;
        float sd = sqrtf(var + 1e-5f);
        g_mean[b * Cn + threadIdx.x] = m;
        g_std [b * Cn + threadIdx.x] = sd;
        smean[threadIdx.x] = m; srstd[threadIdx.x] = 1.f / sd;
    }
    __syncthreads();
    __shared__ float tile[256][33];
    for (int t0 = 0; t0 < Ln; t0 += 256) {
        for (int idx = threadIdx.x; idx < 256 * 32; idx += 256) {
            int t = idx >> 5, cc = idx & 31;
            tile[t][cc] = (xb[(t0 + t) * Cn + cc] - smean[cc]) * srstd[cc];
        }
        __syncthreads();
        for (int idx = threadIdx.x; idx < 32 * 256; idx += 256) {
            int cc = idx >> 8, t = idx & 255;
            float v = tile[t][cc];
            __nv_bfloat16 h = __float2bfloat16(v);
            size_t o = (size_t)b * Cn * Ln + (size_t)cc * Ln + t0 + t;
            g_xnTh[o] = h;
            g_xnTl[o] = __float2bfloat16(v - __bfloat162float(h));
        }
        __syncthreads();
    }
}

// ---------------- cp.async + ldmatrix helpers ----------------
__device__ __forceinline__ void cpa16(uint32_t dst, const void* src) {
    asm volatile("cp.async.cg.shared.global [%0], [%1], 16;" :: "r"(dst), "l"(src));
}
#define CP_COMMIT() asm volatile("cp.async.commit_group;" ::: "memory")
#define CP_WAIT1()  asm volatile("cp.async.wait_group 1;" ::: "memory")
#define CP_WAIT0()  asm volatile("cp.async.wait_group 0;" ::: "memory")

__device__ __forceinline__ void ldsm4(uint32_t& r0, uint32_t& r1, uint32_t& r2, uint32_t& r3, uint32_t a) {
    asm volatile("ldmatrix.sync.aligned.m8n8.x4.shared.b16 {%0,%1,%2,%3}, [%4];"
        : "=r"(r0), "=r"(r1), "=r"(r2), "=r"(r3) : "r"(a));
}
__device__ __forceinline__ void ldsm2(uint32_t& r0, uint32_t& r1, uint32_t a) {
    asm volatile("ldmatrix.sync.aligned.m8n8.x2.shared.b16 {%0,%1}, [%2];"
        : "=r"(r0), "=r"(r1) : "r"(a));
}

#define MMA_OP(c, a0, a1, a2, a3, b0, b1) \
    asm volatile("mma.sync.aligned.m16n8k16.row.col.f32.bf16.bf16.f32 " \
        "{%0,%1,%2,%3}, {%4,%5,%6,%7}, {%8,%9}, {%0,%1,%2,%3};" \
        : "+f"((c)[0]), "+f"((c)[1]), "+f"((c)[2]), "+f"((c)[3]) \
        : "r"(a0), "r"(a1), "r"(a2), "r"(a3), "r"(b0), "r"(b1))

// ---------------- double-buffered split-bf16 HMMA GEMM (ldmatrix fragments) ----------------
template<int BM,int BN,int WM,int WN,bool RELU,bool HASE,bool WF32,bool WSPLIT,bool XIOUT>
__global__ void __launch_bounds__((BM/WM)*(BN/WN)*32, 2)
mgemm2_k(const __nv_bfloat16* __restrict__ Ah, const __nv_bfloat16* __restrict__ Al,
         size_t sA, int ldA, int zAs,
         const __nv_bfloat16* __restrict__ Bh, const __nv_bfloat16* __restrict__ Bl,
         size_t sB, int ldB, int zBm,
         const float* __restrict__ bias, int sBias,
         const float* __restrict__ E, size_t sE, int ldE,
         float* __restrict__ C, __nv_bfloat16* __restrict__ Ch, __nv_bfloat16* __restrict__ Cl,
         size_t sC, int ldC, int K)
{
    constexpr int NWARP = (BM/WM)*(BN/WN);
    constexpr int NT = NWARP * 32;
    constexpr int PAD = 40;
    constexpr int MF = WM / 16, NF = WN / 8;
    constexpr int ABYTES = BM * PAD * 2;
    constexpr int BBYTES = BN * PAD * 2;
    constexpr int STG = 2 * ABYTES + 2 * BBYTES;

    extern __shared__ char dsm[];
    uint32_t smem_base = (uint32_t)__cvta_generic_to_shared(dsm);

    int tid = threadIdx.x, warp = tid >> 5, lane = tid & 31;
    int z = blockIdx.z, m0 = blockIdx.y * BM, n0 = blockIdx.x * BN;

    Ah += (size_t)(z >> zAs) * sA + (size_t)m0 * ldA;
    Al += (size_t)(z >> zAs) * sA + (size_t)m0 * ldA;
    Bh += (size_t)(z & zBm) * sB + (size_t)n0 * ldB;
    Bl += (size_t)(z & zBm) * sB + (size_t)n0 * ldB;

    int wm = warp % (BM / WM), wn = warp / (BM / WM);
    int mB = wm * WM, nB = wn * WN;

    // ldmatrix per-lane geometry
    int g = lane >> 3;
    int aRow = (g & 1) * 8 + (lane & 7);     // row within 16-row A frag group
    int aCol = (g >> 1) * 8;                 // col offset (0 or 8)
    int l15 = lane & 15;
    int bRow = l15 & 7;
    int bCol = (l15 >> 3) * 8;

    float acc[MF][NF][4];
    #pragma unroll
    for (int i = 0; i < MF; i++)
        #pragma unroll
        for (int j = 0; j < NF; j++)
            #pragma unroll
            for (int q = 0; q < 4; q++) acc[i][j][q] = 0.f;

    const int nk = K / 32;
    auto issue = [&](int kt, int stg) {
        int k0 = kt * 32;
        uint32_t base = smem_base + stg * STG;
        #pragma unroll
        for (int j = 0; j < BM * 4 / NT; j++) {
            int idx = tid + j * NT;
            int row = idx >> 2, c8 = idx & 3;
            uint32_t d = base + (uint32_t)(row * PAD + c8 * 8) * 2;
            cpa16(d, Ah + (size_t)row * ldA + k0 + c8 * 8);
            cpa16(d + ABYTES, Al + (size_t)row * ldA + k0 + c8 * 8);
        }
        #pragma unroll
        for (int j = 0; j < BN * 4 / NT; j++) {
            int idx = tid + j * NT;
            int row = idx >> 2, c8 = idx & 3;
            uint32_t d = base + 2 * ABYTES + (uint32_t)(row * PAD + c8 * 8) * 2;
            cpa16(d, Bh + (size_t)row * ldB + k0 + c8 * 8);
            cpa16(d + BBYTES, Bl + (size_t)row * ldB + k0 + c8 * 8);
        }
    };

    issue(0, 0);
    CP_COMMIT();

    for (int kt = 0; kt < nk; kt++) {
        int cur = kt & 1;
        if (kt + 1 < nk) {
            issue(kt + 1, cur ^ 1);
            CP_COMMIT();
            CP_WAIT1();
        } else {
            CP_WAIT0();
        }
        __syncthreads();

        uint32_t sa = smem_base + cur * STG;
        uint32_t sb = sa + 2 * ABYTES;

        #pragma unroll
        for (int ks = 0; ks < 32; ks += 16) {
            uint32_t ah[MF][4], al[MF][4];
            #pragma unroll
            for (int mf = 0; mf < MF; mf++) {
                uint32_t addr = sa + (uint32_t)(((mB + mf * 16 + aRow) * PAD) + ks + aCol) * 2;
                ldsm4(ah[mf][0], ah[mf][1], ah[mf][2], ah[mf][3], addr);
                ldsm4(al[mf][0], al[mf][1], al[mf][2], al[mf][3], addr + ABYTES);
            }
            #pragma unroll
            for (int nf = 0; nf < NF; nf++) {
                uint32_t addr = sb + (uint32_t)(((nB + nf * 8 + bRow) * PAD) + ks + bCol) * 2;
                uint32_t bh0, bh1, bl0, bl1;
                ldsm2(bh0, bh1, addr);
                ldsm2(bl0, bl1, addr + BBYTES);
                #pragma unroll
                for (int mf = 0; mf < MF; mf++) {
                    MMA_OP(acc[mf][nf], ah[mf][0], ah[mf][1], ah[mf][2], ah[mf][3], bh0, bh1);
                    MMA_OP(acc[mf][nf], al[mf][0], al[mf][1], al[mf][2], al[mf][3], bh0, bh1);
                    MMA_OP(acc[mf][nf], ah[mf][0], ah[mf][1], ah[mf][2], ah[mf][3], bl0, bl1);
                }
            }
        }
        __syncthreads();
    }

    // ---- epilogue ----
    if (!XIOUT) {
        size_t cb = (size_t)z * sC + (size_t)m0 * ldC + n0;
        if (WF32) C += cb;
        if (WSPLIT) { Ch += cb; Cl += cb; }
    } else {
        Ch += (size_t)z * sC;
        Cl += (size_t)z * sC;
    }
    if (HASE) E += (size_t)z * sE + (size_t)m0 * ldE + n0;

    #pragma unroll
    for (int mf = 0; mf < MF; mf++) {
        #pragma unroll
        for (int nf = 0; nf < NF; nf++) {
            int r = mB + mf * 16 + (lane >> 2);
            int cc = nB + nf * 8 + (lane & 3) * 2;
            float b0 = 0.f, b1 = 0.f;
            if (bias) {
                b0 = bias[(size_t)z * sBias + n0 + cc];
                b1 = bias[(size_t)z * sBias + n0 + cc + 1];
            }
            float v0 = acc[mf][nf][0] + b0, v1 = acc[mf][nf][1] + b1;
            float v2 = acc[mf][nf][2] + b0, v3 = acc[mf][nf][3] + b1;
            if (HASE) {
                v0 += E[(size_t)r * ldE + cc];       v1 += E[(size_t)r * ldE + cc + 1];
                v2 += E[(size_t)(r + 8) * ldE + cc]; v3 += E[(size_t)(r + 8) * ldE + cc + 1];
            }
            if (RELU) {
                v0 = fmaxf(v0, 0.f); v1 = fmaxf(v1, 0.f);
                v2 = fmaxf(v2, 0.f); v3 = fmaxf(v3, 0.f);
            }
            if (WF32 && !XIOUT) {
                *reinterpret_cast<float2*>(&C[(size_t)r * ldC + cc]) = make_float2(v0, v1);
                *reinterpret_cast<float2*>(&C[(size_t)(r + 8) * ldC + cc]) = make_float2(v2, v3);
            }
            if (WSPLIT || XIOUT) {
                __nv_bfloat162 h01 = __float22bfloat162_rn(make_float2(v0, v1));
                float2 hr01 = __bfloat1622float2(h01);
                __nv_bfloat162 l01 = __float22bfloat162_rn(make_float2(v0 - hr01.x, v1 - hr01.y));
                __nv_bfloat162 h23 = __float22bfloat162_rn(make_float2(v2, v3));
                float2 hr23 = __bfloat1622float2(h23);
                __nv_bfloat162 l23 = __float22bfloat162_rn(make_float2(v2 - hr23.x, v3 - hr23.y));
                if (XIOUT) {
                    int n = n0 + cc;
                    size_t o0 = (size_t)(n >> 5) * (Ln * Cn) + (size_t)(m0 + r) * Cn + (n & 31);
                    size_t o2 = o0 + 8 * Cn;
                    *reinterpret_cast<__nv_bfloat162*>(&Ch[o0]) = h01;
                    *reinterpret_cast<__nv_bfloat162*>(&Cl[o0]) = l01;
                    *reinterpret_cast<__nv_bfloat162*>(&Ch[o2]) = h23;
                    *reinterpret_cast<__nv_bfloat162*>(&Cl[o2]) = l23;
                } else {
                    *reinterpret_cast<__nv_bfloat162*>(&Ch[(size_t)r * ldC + cc]) = h01;
                    *reinterpret_cast<__nv_bfloat162*>(&Cl[(size_t)r * ldC + cc]) = l01;
                    *reinterpret_cast<__nv_bfloat162*>(&Ch[(size_t)(r + 8) * ldC + cc]) = h23;
                    *reinterpret_cast<__nv_bfloat162*>(&Cl[(size_t)(r + 8) * ldC + cc]) = l23;
                }
            }
        }
    }
}

// ---------------- LayerNorm over D (hi/lo in-place) ----------------
__global__ void ln_k(const float* __restrict__ g, const float* __restrict__ bb) {
    int row = blockIdx.x;
    int nb = row >> 10;
    __nv_bfloat16* ph = g_predsh + (size_t)row * Dn;
    __nv_bfloat16* pl = g_predsl + (size_t)row * Dn;
    int tid = threadIdx.x;
    float v[4];
    float s = 0.f, sq = 0.f;
    #pragma unroll
    for (int j = 0; j < 4; j++) {
        int d = tid + j * 128;
        v[j] = __bfloat162float(ph[d]) + __bfloat162float(pl[d]);
        s += v[j]; sq += v[j] * v[j];
    }
    #pragma unroll
    for (int off = 16; off > 0; off >>= 1) {
        s  += __shfl_xor_sync(0xffffffffu, s, off);
        sq += __shfl_xor_sync(0xffffffffu, sq, off);
    }
    __shared__ float rs[4], rq[4];
    if ((tid & 31) == 0) { rs[tid >> 5] = s; rq[tid >> 5] = sq; }
    __syncthreads();
    s = rs[0] + rs[1] + rs[2] + rs[3];
    sq = rq[0] + rq[1] + rq[2] + rq[3];
    float mean = s * (1.f / 512.f);
    float var = sq * (1.f / 512.f) - mean * mean;
    float rstd = rsqrtf(var + 1e-5f);
    #pragma unroll
    for (int j = 0; j < 4; j++) {
        int d = tid + j * 128;
        float o = (v[j] - mean) * rstd * g[nb * Dn + d] + bb[nb * Dn + d];
        __nv_bfloat16 h = __float2bfloat16(o);
        ph[d] = h;
        pl[d] = __float2bfloat16(o - __bfloat162float(h));
    }
}

// ---------------- final: sum blocks, de-normalize ----------------
__global__ void final_k(float* __restrict__ out) {
    size_t i = (size_t)blockIdx.x * 256 + threadIdx.x;
    const size_t TOT = (size_t)Bn * STEPn * SEGn * Cn;
    if (i >= TOT) return;
    int b = (int)(i >> 13);
    int c = (int)(i & 31);
    float a = g_dec2[i] + g_dec2[i + TOT] + g_dec2[i + 2 * TOT] + g_dec2[i + 3 * TOT];
    out[i] = a * g_std[b * Cn + c] + g_mean[b * Cn + c];
}

// ---------------- host ----------------
static inline void* symp(const void* s) { void* p; cudaGetSymbolAddress(&p, s); return p; }

extern "C" void kernel_launch(void* const* d_in, const int* in_sizes, int n_in,
                              void* d_out, int out_size) {
    const float* x_enc = (const float*)d_in[0];
    const float* mw  = (const float*)d_in[4];
    const float* ew1 = (const float*)d_in[5];
    const float* eb1 = (const float*)d_in[6];
    const float* ew2 = (const float*)d_in[7];
    const float* eb2 = (const float*)d_in[8];
    const float* wxh = (const float*)d_in[9];
    const float* whh = (const float*)d_in[10];
    const float* lng = (const float*)d_in[11];
    const float* lnb = (const float*)d_in[12];
    const float* dw1 = (const float*)d_in[13];
    const float* db1 = (const float*)d_in[14];
    const float* dw2 = (const float*)d_in[15];
    const float* db2 = (const float*)d_in[16];
    float* out = (float*)d_out;

    float* p_T     = (float*)symp(g_T);
    float* p_encx  = (float*)symp(g_encx);
    float* p_dec2  = (float*)symp(g_dec2);
    float* p_bfuse = (float*)symp(g_bfuse);
    typedef __nv_bfloat16 bf;
#define SYM2(nm) bf* p_##nm##h = (bf*)symp(g_##nm##h); bf* p_##nm##l = (bf*)symp(g_##nm##l)
    SYM2(T16); SYM2(xnT); SYM2(xi); SYM2(enc1); SYM2(encx16);
    SYM2(hA); SYM2(hB); SYM2(preds); SYM2(dec1);
    SYM2(ew1); SYM2(ew2T); SYM2(wf); SYM2(wxh); SYM2(whh); SYM2(dw1); SYM2(dw2);

    const int SMEMB = 2 * (2 * 128 * 40 * 2 + 2 * 128 * 40 * 2);  // 81920
    auto* fXI  = mgemm2_k<128,128,64,32,false,false,false,true,true>;
    auto* fRS  = mgemm2_k<128,128,64,32,true, false,false,true,false>;
    auto* fS   = mgemm2_k<128,128,64,32,false,false,false,true,false>;
    auto* fES  = mgemm2_k<128,128,64,32,false,true, false,true,false>;
    auto* fFS  = mgemm2_k<128,128,64,32,false,false,true, true,false>;
    auto* fF   = mgemm2_k<128,128,64,32,false,false,true, false,false>;
    cudaFuncSetAttribute((const void*)fXI, cudaFuncAttributeMaxDynamicSharedMemorySize, SMEMB);
    cudaFuncSetAttribute((const void*)fRS, cudaFuncAttributeMaxDynamicSharedMemorySize, SMEMB);
    cudaFuncSetAttribute((const void*)fS,  cudaFuncAttributeMaxDynamicSharedMemorySize, SMEMB);
    cudaFuncSetAttribute((const void*)fES, cudaFuncAttributeMaxDynamicSharedMemorySize, SMEMB);
    cudaFuncSetAttribute((const void*)fFS, cudaFuncAttributeMaxDynamicSharedMemorySize, SMEMB);
    cudaFuncSetAttribute((const void*)fF,  cudaFuncAttributeMaxDynamicSharedMemorySize, SMEMB);

    // ---- prep ----
    cf_k    <<<5, 256>>>(mw);
    rho_k   <<<NBn, 512>>>();
    tbuild_k<<<4096, 256>>>();
    instnorm_k<<<Bn, 256>>>(x_enc);

    split_k<<<(NBn*Ln*Ln +255)/256,256>>>(p_T, p_T16h, p_T16l, NBn*Ln*Ln);
    split_k<<<(NBn*Hn*FINn+255)/256,256>>>(ew1, p_ew1h, p_ew1l, NBn*Hn*FINn);
    split_k<<<(NBn*Dn*Dn +255)/256,256>>>(wxh, p_wxhh, p_wxhl, NBn*Dn*Dn);
    split_k<<<(NBn*Dn*Dn +255)/256,256>>>(whh, p_whhh, p_whhl, NBn*Dn*Dn);
    split_k<<<(NBn*Hn*Dn +255)/256,256>>>(dw1, p_dw1h, p_dw1l, NBn*Hn*Dn);
    split_k<<<(NBn*FINn*Hn+255)/256,256>>>(dw2, p_dw2h, p_dw2l, NBn*FINn*Hn);
    // ew2 [D,H] -> ew2T [H,D] split, for Wfuse GEMM
    tsplit_k<<<dim3(Hn/32, Dn/32, NBn), 256>>>(ew2, p_ew2Th, p_ew2Tl, Dn, Hn);
    bfuse_k<<<(NBn*Dn+255)/256, 256>>>(wxh, eb2);

    // ---- Wfuse = Wxh @ ew2  ([D,H] split; B operand of fused encx GEMM) ----
    fS<<<dim3(Hn/128, Dn/128, NBn), 256, SMEMB>>>(
        p_wxhh, p_wxhl, (size_t)Dn*Dn, Dn, 0,
        p_ew2Th, p_ew2Tl, (size_t)Hn*Dn, Dn, 0x7fffffff,
        nullptr, 0, nullptr, 0, 0,
        nullptr, p_wfh, p_wfl, (size_t)Dn*Hn, Hn, Dn);

    // ---- irfft: xi[nb] = T16[nb] @ xnT^T ----
    fXI<<<dim3((Bn*Cn)/128, Ln/128, NBn), 256, SMEMB>>>(
        p_T16h, p_T16l, (size_t)Ln*Ln, Ln, 0,
        p_xnTh, p_xnTl, 0, Ln, 0,
        nullptr, 0, nullptr, 0, 0,
        nullptr, p_xih, p_xil, (size_t)Bn*Ln*Cn, Cn, Ln);

    // ---- enc L1: relu(xi @ ew1^T + eb1) ----
    fRS<<<dim3(Hn/128, (Bn*FREQn)/128, NBn), 256, SMEMB>>>(
        p_xih, p_xil, (size_t)Bn*Ln*Cn, FINn, 0,
        p_ew1h, p_ew1l, (size_t)Hn*FINn, FINn, 0x7fffffff,
        eb1, Hn, nullptr, 0, 0,
        nullptr, p_enc1h, p_enc1l, (size_t)Bn*FREQn*Hn, Hn, FINn);

    // ---- fused enc L2 + Wxh: encx = enc1 @ Wfuse^T + bfuse ----
    fFS<<<dim3(Dn/128, (Bn*FREQn)/128, NBn), 256, SMEMB>>>(
        p_enc1h, p_enc1l, (size_t)Bn*FREQn*Hn, Hn, 0,
        p_wfh, p_wfl, (size_t)Dn*Hn, Hn, 0x7fffffff,
        p_bfuse, Dn, nullptr, 0, 0,
        p_encx, p_encx16h, p_encx16l, (size_t)Bn*FREQn*Dn, Dn, Hn);

    // ---- RNN: h_t = encx_t + h_{t-1} @ Whh^T ----
    for (int tau = 1; tau < FREQn; tau++) {
        const bf *Aph, *Apl; size_t sAv; int ldAv;
        if (tau == 1) { Aph = p_encx16h; Apl = p_encx16l; sAv = (size_t)Bn*FREQn*Dn; ldAv = FREQn*Dn; }
        else if (tau % 2 == 0) { Aph = p_hAh; Apl = p_hAl; sAv = (size_t)Bn*Dn; ldAv = Dn; }
        else { Aph = p_hBh; Apl = p_hBl; sAv = (size_t)Bn*Dn; ldAv = Dn; }
        bf* Cph = (tau % 2 == 1) ? p_hAh : p_hBh;
        bf* Cpl = (tau % 2 == 1) ? p_hAl : p_hBl;
        fES<<<dim3(Dn/128, Bn/128, NBn), 256, SMEMB>>>(
            Aph, Apl, sAv, ldAv, 0,
            p_whhh, p_whhl, (size_t)Dn*Dn, Dn, 0x7fffffff,
            nullptr, 0,
            p_encx + tau*Dn, (size_t)Bn*FREQn*Dn, FREQn*Dn,
            nullptr, Cph, Cpl, (size_t)Bn*Dn, Dn, Dn);
    }
    // ---- free-run: preds_s = h @ Whh^T (chained; h in hA) ----
    for (int s = 0; s < STEPn; s++) {
        const bf *Aph, *Apl; size_t sAv; int ldAv;
        if (s == 0) { Aph = p_hAh; Apl = p_hAl; sAv = (size_t)Bn*Dn; ldAv = Dn; }
        else { Aph = p_predsh + (s-1)*Dn; Apl = p_predsl + (s-1)*Dn; sAv = (size_t)Bn*STEPn*Dn; ldAv = STEPn*Dn; }
        fS<<<dim3(Dn/128, Bn/128, NBn), 256, SMEMB>>>(
            Aph, Apl, sAv, ldAv, 0,
            p_whhh, p_whhl, (size_t)Dn*Dn, Dn, 0x7fffffff,
            nullptr, 0, nullptr, 0, 0,
            nullptr, p_predsh + s*Dn, p_predsl + s*Dn, (size_t)Bn*STEPn*Dn, STEPn*Dn, Dn);
    }

    ln_k<<<NBn*Bn*STEPn, 128>>>(lng, lnb);

    // ---- dec L1: relu(preds @ dw1^T + db1) ----
    fRS<<<dim3(Hn/128, (Bn*STEPn)/128, NBn), 256, SMEMB>>>(
        p_predsh, p_predsl, (size_t)Bn*STEPn*Dn, Dn, 0,
        p_dw1h, p_dw1l, (size_t)Hn*Dn, Dn, 0x7fffffff,
        db1, Hn, nullptr, 0, 0,
        nullptr, p_dec1h, p_dec1l, (size_t)Bn*STEPn*Hn, Hn, Dn);

    // ---- dec L2 (fp32 out for final_k) ----
    fF<<<dim3(FINn/128, (Bn*STEPn)/128, NBn), 256, SMEMB>>>(
        p_dec1h, p_dec1l, (size_t)Bn*STEPn*Hn, Hn, 0,
        p_dw2h, p_dw2l, (size_t)FINn*Hn, Hn, 0x7fffffff,
        db2, FINn, nullptr, 0, 0,
        p_dec2, nullptr, nullptr, (size_t)Bn*STEPn*FINn, FINn, Hn);

    final_k<<<(Bn*STEPn*SEGn*Cn + 255)/256, 256>>>(out);
}

// round 16
// speedup vs baseline: 1.1971x; 1.1971x over previous
#include <cuda_runtime.h>
#include <cuda_fp16.h>
#include <math.h>
#include <stdint.h>

// ---------------- problem dims ----------------
#define Bn   256
#define Ln   512
#define Cn   32
#define NBn  4
#define SEGn 64
#define FREQn 8
#define STEPn 4
#define Dn   512
#define Hn   1024
#define FINn 2048
#define Fn   257

// ---------------- scratch ----------------
__device__ float g_mean [Bn*Cn];
__device__ float g_std  [Bn*Cn];
__device__ float g_cf   [NBn*Fn];
__device__ float g_rho  [NBn*Ln];
__device__ float g_T    [(size_t)NBn*Ln*Ln];
__device__ float g_encx [(size_t)NBn*Bn*FREQn*Dn];
__device__ float g_dec2 [(size_t)NBn*Bn*STEPn*FINn];

#define BDECL(name, n) __device__ __align__(16) __half name##h[(size_t)(n)], name##l[(size_t)(n)]
BDECL(g_T16,  NBn*Ln*Ln);
BDECL(g_xnT,  Bn*Cn*Ln);
BDECL(g_xi,   (size_t)NBn*Bn*Ln*Cn);
BDECL(g_enc1, (size_t)NBn*Bn*FREQn*Hn);
BDECL(g_enc2, (size_t)NBn*Bn*FREQn*Dn);
BDECL(g_encx16, (size_t)NBn*Bn*FREQn*Dn);
BDECL(g_hA,   NBn*Bn*Dn);
BDECL(g_hB,   NBn*Bn*Dn);
BDECL(g_preds, NBn*Bn*STEPn*Dn);
BDECL(g_dec1, (size_t)NBn*Bn*STEPn*Hn);
BDECL(g_ew1,  (size_t)NBn*Hn*FINn);
BDECL(g_ew2,  (size_t)NBn*Dn*Hn);
BDECL(g_wxh,  NBn*Dn*Dn);
BDECL(g_whh,  NBn*Dn*Dn);
BDECL(g_dw1,  (size_t)NBn*Hn*Dn);
BDECL(g_dw2,  (size_t)NBn*FINn*Hn);

// ---------------- prep kernels ----------------
__global__ void cf_k(const float* __restrict__ mw) {
    int i = blockIdx.x * 256 + threadIdx.x;
    if (i < NBn * Fn) g_cf[i] = 1.f / (1.f + expf(-mw[i]));
}
__global__ void rho_k() {
    int nb = blockIdx.x, d = threadIdx.x;
    const float* cf = g_cf + nb * Fn;
    const float ST = 6.28318530717958647692f / 512.f;
    float s = cf[0] + ((d & 1) ? -cf[256] : cf[256]);
    for (int k = 1; k <= 255; k++)
        s += 2.f * cf[k] * cosf((float)((k * d) & 511) * ST);
    g_rho[nb * Ln + d] = s * (1.f / 512.f);
}
__global__ void tbuild_k() {
    int i = blockIdx.x * 256 + threadIdx.x;
    int nb = i >> 18, t = (i >> 9) & 511, tp = i & 511;
    g_T[i] = g_rho[nb * Ln + ((t - tp) & 511)];
}
__global__ void split_k(const float* __restrict__ s, __half* __restrict__ h,
                        __half* __restrict__ l, int n) {
    int i = blockIdx.x * 256 + threadIdx.x;
    if (i >= n) return;
    float v = s[i];
    __half hh = __float2half(v);
    h[i] = hh;
    l[i] = __float2half(v - __half2float(hh));
}

// ---------------- instance norm + transposed split-fp16 write ----------------
__global__ void instnorm_k(const float* __restrict__ x) {
    int b = blockIdx.x;
    int c = threadIdx.x & 31, r = threadIdx.x >> 5;
    const float* xb = x + (size_t)b * Ln * Cn;
    float s = 0.f, sq = 0.f;
    for (int t = r; t < Ln; t += 8) { float v = xb[t * Cn + c]; s += v; sq += v * v; }
    __shared__ float ss[8][32], sg[8][32], smean[32], srstd[32];
    ss[r][c] = s; sg[r][c] = sq;
    __syncthreads();
    if (threadIdx.x < 32) {
        float a = 0.f, q = 0.f;
        #pragma unroll
        for (int j = 0; j < 8; j++) { a += ss[j][threadIdx.x]; q += sg[j][threadIdx.x]; }
        float m = a * (1.f / 512.f);
        float var = q * (1.f / 512.f) - m * m;
        float sd = sqrtf(var + 1e-5f);
        g_mean[b * Cn + threadIdx.x] = m;
        g_std [b * Cn + threadIdx.x] = sd;
        smean[threadIdx.x] = m; srstd[threadIdx.x] = 1.f / sd;
    }
    __syncthreads();
    __shared__ float tile[256][33];
    for (int t0 = 0; t0 < Ln; t0 += 256) {
        for (int idx = threadIdx.x; idx < 256 * 32; idx += 256) {
            int t = idx >> 5, cc = idx & 31;
            tile[t][cc] = (xb[(t0 + t) * Cn + cc] - smean[cc]) * srstd[cc];
        }
        __syncthreads();
        for (int idx = threadIdx.x; idx < 32 * 256; idx += 256) {
            int cc = idx >> 8, t = idx & 255;
            float v = tile[t][cc];
            __half h = __float2half(v);
            size_t o = (size_t)b * Cn * Ln + (size_t)cc * Ln + t0 + t;
            g_xnTh[o] = h;
            g_xnTl[o] = __float2half(v - __half2float(h));
        }
        __syncthreads();
    }
}

// ---------------- cp.async helpers ----------------
__device__ __forceinline__ void cpa16(uint32_t dst, const void* src) {
    asm volatile("cp.async.cg.shared.global [%0], [%1], 16;" :: "r"(dst), "l"(src));
}
#define CP_COMMIT() asm volatile("cp.async.commit_group;" ::: "memory")
#define CP_WAIT1()  asm volatile("cp.async.wait_group 1;" ::: "memory")
#define CP_WAIT0()  asm volatile("cp.async.wait_group 0;" ::: "memory")

#define MMA_OP(c, a0, a1, a2, a3, b0, b1) \
    asm volatile("mma.sync.aligned.m16n8k16.row.col.f32.f16.f16.f32 " \
        "{%0,%1,%2,%3}, {%4,%5,%6,%7}, {%8,%9}, {%0,%1,%2,%3};" \
        : "+f"((c)[0]), "+f"((c)[1]), "+f"((c)[2]), "+f"((c)[3]) \
        : "r"(a0), "r"(a1), "r"(a2), "r"(a3), "r"(b0), "r"(b1))

// ---------------- double-buffered split-fp16 HMMA GEMM ----------------
// NMMA=3: AhBh + AlBh + AhBl (full compensation). NMMA=2: AhBh + AlBh (B hi-only).
template<int BM,int BN,int WM,int WN,int NMMA,bool RELU,bool HASE,bool WF32,bool WSPLIT,bool XIOUT>
__global__ void __launch_bounds__((BM/WM)*(BN/WN)*32, 2)
mgemm2_k(const __half* __restrict__ Ah, const __half* __restrict__ Al,
         size_t sA, int ldA, int zAs,
         const __half* __restrict__ Bh, const __half* __restrict__ Bl,
         size_t sB, int ldB, int zBm,
         const float* __restrict__ bias, int sBias,
         const float* __restrict__ E, size_t sE, int ldE,
         float* __restrict__ C, __half* __restrict__ Ch, __half* __restrict__ Cl,
         size_t sC, int ldC, int K)
{
    constexpr int NWARP = (BM/WM)*(BN/WN);
    constexpr int NT = NWARP * 32;
    constexpr int PAD = 40;
    constexpr int MF = WM / 16, NF = WN / 8;
    constexpr int ABYTES = BM * PAD * 2;
    constexpr int BBYTES = BN * PAD * 2;
    constexpr int STG = 2 * ABYTES + 2 * BBYTES;

    extern __shared__ char dsm[];
    uint32_t smem_base = (uint32_t)__cvta_generic_to_shared(dsm);

    int tid = threadIdx.x, warp = tid >> 5, lane = tid & 31;
    int z = blockIdx.z, m0 = blockIdx.y * BM, n0 = blockIdx.x * BN;

    Ah += (size_t)(z >> zAs) * sA + (size_t)m0 * ldA;
    Al += (size_t)(z >> zAs) * sA + (size_t)m0 * ldA;
    Bh += (size_t)(z & zBm) * sB + (size_t)n0 * ldB;
    Bl += (size_t)(z & zBm) * sB + (size_t)n0 * ldB;

    int wm = warp % (BM / WM), wn = warp / (BM / WM);
    int mB = wm * WM, nB = wn * WN;

    float acc[MF][NF][4];
    #pragma unroll
    for (int i = 0; i < MF; i++)
        #pragma unroll
        for (int j = 0; j < NF; j++)
            #pragma unroll
            for (int q = 0; q < 4; q++) acc[i][j][q] = 0.f;

    const int nk = K / 32;
    auto issue = [&](int kt, int stg) {
        int k0 = kt * 32;
        uint32_t base = smem_base + stg * STG;
        #pragma unroll
        for (int j = 0; j < BM * 4 / NT; j++) {
            int idx = tid + j * NT;
            int row = idx >> 2, c8 = idx & 3;
            uint32_t d = base + (uint32_t)(row * PAD + c8 * 8) * 2;
            cpa16(d, Ah + (size_t)row * ldA + k0 + c8 * 8);
            cpa16(d + ABYTES, Al + (size_t)row * ldA + k0 + c8 * 8);
        }
        #pragma unroll
        for (int j = 0; j < BN * 4 / NT; j++) {
            int idx = tid + j * NT;
            int row = idx >> 2, c8 = idx & 3;
            uint32_t d = base + 2 * ABYTES + (uint32_t)(row * PAD + c8 * 8) * 2;
            cpa16(d, Bh + (size_t)row * ldB + k0 + c8 * 8);
            if (NMMA == 3) cpa16(d + BBYTES, Bl + (size_t)row * ldB + k0 + c8 * 8);
        }
    };

    issue(0, 0);
    CP_COMMIT();

    for (int kt = 0; kt < nk; kt++) {
        int cur = kt & 1;
        if (kt + 1 < nk) {
            issue(kt + 1, cur ^ 1);
            CP_COMMIT();
            CP_WAIT1();
        } else {
            CP_WAIT0();
        }
        __syncthreads();

        const __half* sAh = (const __half*)(dsm + cur * STG);
        const __half* sAl = sAh + BM * PAD;
        const __half* sBh = (const __half*)(dsm + cur * STG + 2 * ABYTES);
        const __half* sBl = sBh + BN * PAD;

        #pragma unroll
        for (int ks = 0; ks < 32; ks += 16) {
            int kk = ks + (lane & 3) * 2;
            int r0 = mB + (lane >> 2);
            uint32_t ah[MF][4], al[MF][4];
            #pragma unroll
            for (int mf = 0; mf < MF; mf++) {
                int r = r0 + mf * 16;
                ah[mf][0] = *reinterpret_cast<const uint32_t*>(&sAh[r * PAD + kk]);
                ah[mf][1] = *reinterpret_cast<const uint32_t*>(&sAh[(r + 8) * PAD + kk]);
                ah[mf][2] = *reinterpret_cast<const uint32_t*>(&sAh[r * PAD + kk + 8]);
                ah[mf][3] = *reinterpret_cast<const uint32_t*>(&sAh[(r + 8) * PAD + kk + 8]);
                al[mf][0] = *reinterpret_cast<const uint32_t*>(&sAl[r * PAD + kk]);
                al[mf][1] = *reinterpret_cast<const uint32_t*>(&sAl[(r + 8) * PAD + kk]);
                al[mf][2] = *reinterpret_cast<const uint32_t*>(&sAl[r * PAD + kk + 8]);
                al[mf][3] = *reinterpret_cast<const uint32_t*>(&sAl[(r + 8) * PAD + kk + 8]);
            }
            #pragma unroll
            for (int nf = 0; nf < NF; nf++) {
                int cB = nB + nf * 8 + (lane >> 2);
                uint32_t bh0 = *reinterpret_cast<const uint32_t*>(&sBh[cB * PAD + kk]);
                uint32_t bh1 = *reinterpret_cast<const uint32_t*>(&sBh[cB * PAD + kk + 8]);
                uint32_t bl0 = 0, bl1 = 0;
                if (NMMA == 3) {
                    bl0 = *reinterpret_cast<const uint32_t*>(&sBl[cB * PAD + kk]);
                    bl1 = *reinterpret_cast<const uint32_t*>(&sBl[cB * PAD + kk + 8]);
                }
                #pragma unroll
                for (int mf = 0; mf < MF; mf++) {
                    MMA_OP(acc[mf][nf], ah[mf][0], ah[mf][1], ah[mf][2], ah[mf][3], bh0, bh1);
                    MMA_OP(acc[mf][nf], al[mf][0], al[mf][1], al[mf][2], al[mf][3], bh0, bh1);
                    if (NMMA == 3)
                        MMA_OP(acc[mf][nf], ah[mf][0], ah[mf][1], ah[mf][2], ah[mf][3], bl0, bl1);
                }
            }
        }
        __syncthreads();
    }

    // ---- epilogue ----
    if (!XIOUT) {
        size_t cb = (size_t)z * sC + (size_t)m0 * ldC + n0;
        if (WF32) C += cb;
        if (WSPLIT) { Ch += cb; Cl += cb; }
    } else {
        Ch += (size_t)z * sC;
        Cl += (size_t)z * sC;
    }
    if (HASE) E += (size_t)z * sE + (size_t)m0 * ldE + n0;

    #pragma unroll
    for (int mf = 0; mf < MF; mf++) {
        #pragma unroll
        for (int nf = 0; nf < NF; nf++) {
            int r = mB + mf * 16 + (lane >> 2);
            int cc = nB + nf * 8 + (lane & 3) * 2;
            float b0 = 0.f, b1 = 0.f;
            if (bias) {
                b0 = bias[(size_t)z * sBias + n0 + cc];
                b1 = bias[(size_t)z * sBias + n0 + cc + 1];
            }
            float v0 = acc[mf][nf][0] + b0, v1 = acc[mf][nf][1] + b1;
            float v2 = acc[mf][nf][2] + b0, v3 = acc[mf][nf][3] + b1;
            if (HASE) {
                v0 += E[(size_t)r * ldE + cc];       v1 += E[(size_t)r * ldE + cc + 1];
                v2 += E[(size_t)(r + 8) * ldE + cc]; v3 += E[(size_t)(r + 8) * ldE + cc + 1];
            }
            if (RELU) {
                v0 = fmaxf(v0, 0.f); v1 = fmaxf(v1, 0.f);
                v2 = fmaxf(v2, 0.f); v3 = fmaxf(v3, 0.f);
            }
            if (WF32 && !XIOUT) {
                *reinterpret_cast<float2*>(&C[(size_t)r * ldC + cc]) = make_float2(v0, v1);
                *reinterpret_cast<float2*>(&C[(size_t)(r + 8) * ldC + cc]) = make_float2(v2, v3);
            }
            if (WSPLIT || XIOUT) {
                __half2 h01 = __float22half2_rn(make_float2(v0, v1));
                float2 hr01 = __half22float2(h01);
                __half2 l01 = __float22half2_rn(make_float2(v0 - hr01.x, v1 - hr01.y));
                __half2 h23 = __float22half2_rn(make_float2(v2, v3));
                float2 hr23 = __half22float2(h23);
                __half2 l23 = __float22half2_rn(make_float2(v2 - hr23.x, v3 - hr23.y));
                if (XIOUT) {
                    int n = n0 + cc;
                    size_t o0 = (size_t)(n >> 5) * (Ln * Cn) + (size_t)(m0 + r) * Cn + (n & 31);
                    size_t o2 = o0 + 8 * Cn;
                    *reinterpret_cast<__half2*>(&Ch[o0]) = h01;
                    *reinterpret_cast<__half2*>(&Cl[o0]) = l01;
                    *reinterpret_cast<__half2*>(&Ch[o2]) = h23;
                    *reinterpret_cast<__half2*>(&Cl[o2]) = l23;
                } else {
                    *reinterpret_cast<__half2*>(&Ch[(size_t)r * ldC + cc]) = h01;
                    *reinterpret_cast<__half2*>(&Cl[(size_t)r * ldC + cc]) = l01;
                    *reinterpret_cast<__half2*>(&Ch[(size_t)(r + 8) * ldC + cc]) = h23;
                    *reinterpret_cast<__half2*>(&Cl[(size_t)(r + 8) * ldC + cc]) = l23;
                }
            }
        }
    }
}

// ---------------- LayerNorm over D (hi/lo in-place) ----------------
__global__ void ln_k(const float* __restrict__ g, const float* __restrict__ bb) {
    int row = blockIdx.x;
    int nb = row >> 10;
    __half* ph = g_predsh + (size_t)row * Dn;
    __half* pl = g_predsl + (size_t)row * Dn;
    int tid = threadIdx.x;
    float v[4];
    float s = 0.f, sq = 0.f;
    #pragma unroll
    for (int j = 0; j < 4; j++) {
        int d = tid + j * 128;
        v[j] = __half2float(ph[d]) + __half2float(pl[d]);
        s += v[j]; sq += v[j] * v[j];
    }
    #pragma unroll
    for (int off = 16; off > 0; off >>= 1) {
        s  += __shfl_xor_sync(0xffffffffu, s, off);
        sq += __shfl_xor_sync(0xffffffffu, sq, off);
    }
    __shared__ float rs[4], rq[4];
    if ((tid & 31) == 0) { rs[tid >> 5] = s; rq[tid >> 5] = sq; }
    __syncthreads();
    s = rs[0] + rs[1] + rs[2] + rs[3];
    sq = rq[0] + rq[1] + rq[2] + rq[3];
    float mean = s * (1.f / 512.f);
    float var = sq * (1.f / 512.f) - mean * mean;
    float rstd = rsqrtf(var + 1e-5f);
    #pragma unroll
    for (int j = 0; j < 4; j++) {
        int d = tid + j * 128;
        float o = (v[j] - mean) * rstd * g[nb * Dn + d] + bb[nb * Dn + d];
        __half h = __float2half(o);
        ph[d] = h;
        pl[d] = __float2half(o - __half2float(h));
    }
}

// ---------------- final: sum blocks, de-normalize ----------------
__global__ void final_k(float* __restrict__ out) {
    size_t i = (size_t)blockIdx.x * 256 + threadIdx.x;
    const size_t TOT = (size_t)Bn * STEPn * SEGn * Cn;
    if (i >= TOT) return;
    int b = (int)(i >> 13);
    int c = (int)(i & 31);
    float a = g_dec2[i] + g_dec2[i + TOT] + g_dec2[i + 2 * TOT] + g_dec2[i + 3 * TOT];
    out[i] = a * g_std[b * Cn + c] + g_mean[b * Cn + c];
}

// ---------------- host ----------------
static inline void* symp(const void* s) { void* p; cudaGetSymbolAddress(&p, s); return p; }

extern "C" void kernel_launch(void* const* d_in, const int* in_sizes, int n_in,
                              void* d_out, int out_size) {
    const float* x_enc = (const float*)d_in[0];
    const float* mw  = (const float*)d_in[4];
    const float* ew1 = (const float*)d_in[5];
    const float* eb1 = (const float*)d_in[6];
    const float* ew2 = (const float*)d_in[7];
    const float* eb2 = (const float*)d_in[8];
    const float* wxh = (const float*)d_in[9];
    const float* whh = (const float*)d_in[10];
    const float* lng = (const float*)d_in[11];
    const float* lnb = (const float*)d_in[12];
    const float* dw1 = (const float*)d_in[13];
    const float* db1 = (const float*)d_in[14];
    const float* dw2 = (const float*)d_in[15];
    const float* db2 = (const float*)d_in[16];
    float* out = (float*)d_out;

    float* p_T    = (float*)symp(g_T);
    float* p_encx = (float*)symp(g_encx);
    float* p_dec2 = (float*)symp(g_dec2);
    typedef __half hf;
#define SYM2(nm) hf* p_##nm##h = (hf*)symp(g_##nm##h); hf* p_##nm##l = (hf*)symp(g_##nm##l)
    SYM2(T16); SYM2(xnT); SYM2(xi); SYM2(enc1); SYM2(enc2); SYM2(encx16);
    SYM2(hA); SYM2(hB); SYM2(preds); SYM2(dec1);
    SYM2(ew1); SYM2(ew2); SYM2(wxh); SYM2(whh); SYM2(dw1); SYM2(dw2);

    const int SMEMB = 2 * (2 * 128 * 40 * 2 + 2 * 128 * 40 * 2);  // 81920
    auto* fXI2 = mgemm2_k<128,128,64,32,2,false,false,false,true,true>;
    auto* fRS2 = mgemm2_k<128,128,64,32,2,true, false,false,true,false>;
    auto* fS3  = mgemm2_k<128,128,64,32,3,false,false,false,true,false>;
    auto* fES3 = mgemm2_k<128,128,64,32,3,false,true, false,true,false>;
    auto* fFS3 = mgemm2_k<128,128,64,32,3,false,false,true, true,false>;
    auto* fF2  = mgemm2_k<128,128,64,32,2,false,false,true, false,false>;
    cudaFuncSetAttribute((const void*)fXI2, cudaFuncAttributeMaxDynamicSharedMemorySize, SMEMB);
    cudaFuncSetAttribute((const void*)fRS2, cudaFuncAttributeMaxDynamicSharedMemorySize, SMEMB);
    cudaFuncSetAttribute((const void*)fS3,  cudaFuncAttributeMaxDynamicSharedMemorySize, SMEMB);
    cudaFuncSetAttribute((const void*)fES3, cudaFuncAttributeMaxDynamicSharedMemorySize, SMEMB);
    cudaFuncSetAttribute((const void*)fFS3, cudaFuncAttributeMaxDynamicSharedMemorySize, SMEMB);
    cudaFuncSetAttribute((const void*)fF2,  cudaFuncAttributeMaxDynamicSharedMemorySize, SMEMB);

    // ---- prep ----
    cf_k    <<<5, 256>>>(mw);
    rho_k   <<<NBn, 512>>>();
    tbuild_k<<<4096, 256>>>();
    instnorm_k<<<Bn, 256>>>(x_enc);

    split_k<<<(NBn*Ln*Ln +255)/256,256>>>(p_T, p_T16h, p_T16l, NBn*Ln*Ln);
    split_k<<<(NBn*Hn*FINn+255)/256,256>>>(ew1, p_ew1h, p_ew1l, NBn*Hn*FINn);
    split_k<<<(NBn*Dn*Hn +255)/256,256>>>(ew2, p_ew2h, p_ew2l, NBn*Dn*Hn);
    split_k<<<(NBn*Dn*Dn +255)/256,256>>>(wxh, p_wxhh, p_wxhl, NBn*Dn*Dn);
    split_k<<<(NBn*Dn*Dn +255)/256,256>>>(whh, p_whhh, p_whhl, NBn*Dn*Dn);
    split_k<<<(NBn*Hn*Dn +255)/256,256>>>(dw1, p_dw1h, p_dw1l, NBn*Hn*Dn);
    split_k<<<(NBn*FINn*Hn+255)/256,256>>>(dw2, p_dw2h, p_dw2l, NBn*FINn*Hn);

    // ---- irfft: xi[nb] = T16[nb] @ xnT^T  (2-MMA) ----
    fXI2<<<dim3((Bn*Cn)/128, Ln/128, NBn), 256, SMEMB>>>(
        p_T16h, p_T16l, (size_t)Ln*Ln, Ln, 0,
        p_xnTh, p_xnTl, 0, Ln, 0,
        nullptr, 0, nullptr, 0, 0,
        nullptr, p_xih, p_xil, (size_t)Bn*Ln*Cn, Cn, Ln);

    // ---- enc L1: relu(xi @ ew1^T + eb1)  (2-MMA) ----
    fRS2<<<dim3(Hn/128, (Bn*FREQn)/128, NBn), 256, SMEMB>>>(
        p_xih, p_xil, (size_t)Bn*Ln*Cn, FINn, 0,
        p_ew1h, p_ew1l, (size_t)Hn*FINn, FINn, 0x7fffffff,
        eb1, Hn, nullptr, 0, 0,
        nullptr, p_enc1h, p_enc1l, (size_t)Bn*FREQn*Hn, Hn, FINn);

    // ---- enc L2 (3-MMA) ----
    fS3<<<dim3(Dn/128, (Bn*FREQn)/128, NBn), 256, SMEMB>>>(
        p_enc1h, p_enc1l, (size_t)Bn*FREQn*Hn, Hn, 0,
        p_ew2h, p_ew2l, (size_t)Dn*Hn, Hn, 0x7fffffff,
        eb2, Dn, nullptr, 0, 0,
        nullptr, p_enc2h, p_enc2l, (size_t)Bn*FREQn*Dn, Dn, Hn);

    // ---- encx = enc @ Wxh^T (3-MMA; fp32 + split out) ----
    fFS3<<<dim3(Dn/128, (Bn*FREQn)/128, NBn), 256, SMEMB>>>(
        p_enc2h, p_enc2l, (size_t)Bn*FREQn*Dn, Dn, 0,
        p_wxhh, p_wxhl, (size_t)Dn*Dn, Dn, 0x7fffffff,
        nullptr, 0, nullptr, 0, 0,
        p_encx, p_encx16h, p_encx16l, (size_t)Bn*FREQn*Dn, Dn, Dn);

    // ---- RNN: h_t = encx_t + h_{t-1} @ Whh^T (3-MMA) ----
    for (int tau = 1; tau < FREQn; tau++) {
        const hf *Aph, *Apl; size_t sAv; int ldAv;
        if (tau == 1) { Aph = p_encx16h; Apl = p_encx16l; sAv = (size_t)Bn*FREQn*Dn; ldAv = FREQn*Dn; }
        else if (tau % 2 == 0) { Aph = p_hAh; Apl = p_hAl; sAv = (size_t)Bn*Dn; ldAv = Dn; }
        else { Aph = p_hBh; Apl = p_hBl; sAv = (size_t)Bn*Dn; ldAv = Dn; }
        hf* Cph = (tau % 2 == 1) ? p_hAh : p_hBh;
        hf* Cpl = (tau % 2 == 1) ? p_hAl : p_hBl;
        fES3<<<dim3(Dn/128, Bn/128, NBn), 256, SMEMB>>>(
            Aph, Apl, sAv, ldAv, 0,
            p_whhh, p_whhl, (size_t)Dn*Dn, Dn, 0x7fffffff,
            nullptr, 0,
            p_encx + tau*Dn, (size_t)Bn*FREQn*Dn, FREQn*Dn,
            nullptr, Cph, Cpl, (size_t)Bn*Dn, Dn, Dn);
    }
    // ---- free-run: preds_s = h @ Whh^T (chained; 3-MMA) ----
    for (int s = 0; s < STEPn; s++) {
        const hf *Aph, *Apl; size_t sAv; int ldAv;
        if (s == 0) { Aph = p_hAh; Apl = p_hAl; sAv = (size_t)Bn*Dn; ldAv = Dn; }
        else { Aph = p_predsh + (s-1)*Dn; Apl = p_predsl + (s-1)*Dn; sAv = (size_t)Bn*STEPn*Dn; ldAv = STEPn*Dn; }
        fS3<<<dim3(Dn/128, Bn/128, NBn), 256, SMEMB>>>(
            Aph, Apl, sAv, ldAv, 0,
            p_whhh, p_whhl, (size_t)Dn*Dn, Dn, 0x7fffffff,
            nullptr, 0, nullptr, 0, 0,
            nullptr, p_predsh + s*Dn, p_predsl + s*Dn, (size_t)Bn*STEPn*Dn, STEPn*Dn, Dn);
    }

    ln_k<<<NBn*Bn*STEPn, 128>>>(lng, lnb);

    // ---- dec L1: relu(preds @ dw1^T + db1)  (2-MMA) ----
    fRS2<<<dim3(Hn/128, (Bn*STEPn)/128, NBn), 256, SMEMB>>>(
        p_predsh, p_predsl, (size_t)Bn*STEPn*Dn, Dn, 0,
        p_dw1h, p_dw1l, (size_t)Hn*Dn, Dn, 0x7fffffff,
        db1, Hn, nullptr, 0, 0,
        nullptr, p_dec1h, p_dec1l, (size_t)Bn*STEPn*Hn, Hn, Dn);

    // ---- dec L2 (2-MMA; fp32 out) ----
    fF2<<<dim3(FINn/128, (Bn*STEPn)/128, NBn), 256, SMEMB>>>(
        p_dec1h, p_dec1l, (size_t)Bn*STEPn*Hn, Hn, 0,
        p_dw2h, p_dw2l, (size_t)FINn*Hn, Hn, 0x7fffffff,
        db2, FINn, nullptr, 0, 0,
        p_dec2, nullptr, nullptr, (size_t)Bn*STEPn*FINn, FINn, Hn);

    final_k<<<(Bn*STEPn*SEGn*Cn + 255)/256, 256>>>(out);
}

// round 17
// speedup vs baseline: 1.2902x; 1.0777x over previous
#include <cuda_runtime.h>
#include <cuda_fp16.h>
#include <math.h>
#include <stdint.h>

// ---------------- problem dims ----------------
#define Bn   256
#define Ln   512
#define Cn   32
#define NBn  4
#define SEGn 64
#define FREQn 8
#define STEPn 4
#define Dn   512
#define Hn   1024
#define FINn 2048
#define Fn   257

// ---------------- scratch ----------------
__device__ float g_mean [Bn*Cn];
__device__ float g_std  [Bn*Cn];
__device__ float g_cf   [NBn*Fn];
__device__ float g_rho  [NBn*Ln];
__device__ float g_encx [(size_t)NBn*Bn*FREQn*Dn];
__device__ float g_U32  [(size_t)NBn*Bn*4*Dn];
__device__ float g_dec2 [(size_t)NBn*Bn*STEPn*FINn];

#define BDECL(name, n) __device__ __align__(16) __half name##h[(size_t)(n)], name##l[(size_t)(n)]
BDECL(g_T16,  NBn*Ln*Ln);
BDECL(g_xnT,  Bn*Cn*Ln);
BDECL(g_xi,   (size_t)NBn*Bn*Ln*Cn);
BDECL(g_enc1, (size_t)NBn*Bn*FREQn*Hn);
BDECL(g_enc2, (size_t)NBn*Bn*FREQn*Dn);
BDECL(g_encx16, (size_t)NBn*Bn*FREQn*Dn);
BDECL(g_U,    (size_t)NBn*Bn*4*Dn);
BDECL(g_hA,   NBn*Bn*Dn);
BDECL(g_hB,   NBn*Bn*Dn);
BDECL(g_preds, NBn*Bn*STEPn*Dn);
BDECL(g_dec1, (size_t)NBn*Bn*STEPn*Hn);
BDECL(g_ew1,  (size_t)NBn*Hn*FINn);
BDECL(g_ew2,  (size_t)NBn*Dn*Hn);
BDECL(g_wxh,  NBn*Dn*Dn);
BDECL(g_whhT, NBn*Dn*Dn);
BDECL(g_pw,   (size_t)NBn*4*Dn*Dn);   // [Whh; Whh^2; Whh^3; Whh^4] per nb
BDECL(g_dw1,  (size_t)NBn*Hn*Dn);
BDECL(g_dw2,  (size_t)NBn*FINn*Hn);

// ---------------- prep kernels ----------------
__global__ void cf_k(const float* __restrict__ mw) {
    int i = blockIdx.x * 256 + threadIdx.x;
    if (i < NBn * Fn) g_cf[i] = 1.f / (1.f + expf(-mw[i]));
}
__global__ void rho_k() {
    int nb = blockIdx.x, d = threadIdx.x;
    const float* cf = g_cf + nb * Fn;
    const float ST = 6.28318530717958647692f / 512.f;
    float s = cf[0] + ((d & 1) ? -cf[256] : cf[256]);
    for (int k = 1; k <= 255; k++)
        s += 2.f * cf[k] * cosf((float)((k * d) & 511) * ST);
    g_rho[nb * Ln + d] = s * (1.f / 512.f);
}
// build T = circulant(rho), split fp16 directly (no fp32 intermediate)
__global__ void tbuild_k() {
    int i = blockIdx.x * 256 + threadIdx.x;
    int nb = i >> 18, t = (i >> 9) & 511, tp = i & 511;
    float v = g_rho[nb * Ln + ((t - tp) & 511)];
    __half h = __float2half(v);
    g_T16h[i] = h;
    g_T16l[i] = __float2half(v - __half2float(h));
}
__global__ void split_k(const float* __restrict__ s, __half* __restrict__ h,
                        __half* __restrict__ l, int n) {
    int i = blockIdx.x * 256 + threadIdx.x;
    if (i >= n) return;
    float v = s[i];
    __half hh = __float2half(v);
    h[i] = hh;
    l[i] = __float2half(v - __half2float(hh));
}
// split whh [nb][D][D] into pw slot 0 of [nb][4D][D]
__global__ void splitcp_k(const float* __restrict__ s) {
    int i = blockIdx.x * 256 + threadIdx.x;
    if (i >= NBn * Dn * Dn) return;
    int nb = i / (Dn * Dn), rem = i - nb * Dn * Dn;
    float v = s[i];
    __half hh = __float2half(v);
    size_t o = (size_t)nb * 4 * Dn * Dn + rem;
    g_pwh[o] = hh;
    g_pwl[o] = __float2half(v - __half2float(hh));
}
// transpose + split: src [z][R][Cc] fp32 -> out [z][Cc][R] fp16 hi/lo
__global__ void tsplit_k(const float* __restrict__ src, __half* __restrict__ th,
                         __half* __restrict__ tl, int R, int Cc) {
    __shared__ float t[32][33];
    int z = blockIdx.z;
    int r0 = blockIdx.y * 32, c0 = blockIdx.x * 32;
    int tx = threadIdx.x & 31, ty = threadIdx.x >> 5;
    const float* s = src + (size_t)z * R * Cc;
    #pragma unroll
    for (int j = 0; j < 32; j += 8)
        t[ty + j][tx] = s[(size_t)(r0 + ty + j) * Cc + c0 + tx];
    __syncthreads();
    __half* oh = th + (size_t)z * R * Cc;
    __half* ol = tl + (size_t)z * R * Cc;
    #pragma unroll
    for (int j = 0; j < 32; j += 8) {
        float v = t[tx][ty + j];
        __half h = __float2half(v);
        size_t o = (size_t)(c0 + ty + j) * R + r0 + tx;
        oh[o] = h;
        ol[o] = __float2half(v - __half2float(h));
    }
}

// ---------------- instance norm + transposed split-fp16 write ----------------
__global__ void instnorm_k(const float* __restrict__ x) {
    int b = blockIdx.x;
    int c = threadIdx.x & 31, r = threadIdx.x >> 5;
    const float* xb = x + (size_t)b * Ln * Cn;
    float s = 0.f, sq = 0.f;
    for (int t = r; t < Ln; t += 8) { float v = xb[t * Cn + c]; s += v; sq += v * v; }
    __shared__ float ss[8][32], sg[8][32], smean[32], srstd[32];
    ss[r][c] = s; sg[r][c] = sq;
    __syncthreads();
    if (threadIdx.x < 32) {
        float a = 0.f, q = 0.f;
        #pragma unroll
        for (int j = 0; j < 8; j++) { a += ss[j][threadIdx.x]; q += sg[j][threadIdx.x]; }
        float m = a * (1.f / 512.f);
        float var = q * (1.f / 512.f) - m * m;
        float sd = sqrtf(var + 1e-5f);
        g_mean[b * Cn + threadIdx.x] = m;
        g_std [b * Cn + threadIdx.x] = sd;
        smean[threadIdx.x] = m; srstd[threadIdx.x] = 1.f / sd;
    }
    __syncthreads();
    __shared__ float tile[256][33];
    for (int t0 = 0; t0 < Ln; t0 += 256) {
        for (int idx = threadIdx.x; idx < 256 * 32; idx += 256) {
            int t = idx >> 5, cc = idx & 31;
            tile[t][cc] = (xb[(t0 + t) * Cn + cc] - smean[cc]) * srstd[cc];
        }
        __syncthreads();
        for (int idx = threadIdx.x; idx < 32 * 256; idx += 256) {
            int cc = idx >> 8, t = idx & 255;
            float v = tile[t][cc];
            __half h = __float2half(v);
            size_t o = (size_t)b * Cn * Ln + (size_t)cc * Ln + t0 + t;
            g_xnTh[o] = h;
            g_xnTl[o] = __float2half(v - __half2float(h));
        }
        __syncthreads();
    }
}

// ---------------- cp.async helpers ----------------
__device__ __forceinline__ void cpa16(uint32_t dst, const void* src) {
    asm volatile("cp.async.cg.shared.global [%0], [%1], 16;" :: "r"(dst), "l"(src));
}
#define CP_COMMIT() asm volatile("cp.async.commit_group;" ::: "memory")
#define CP_WAIT1()  asm volatile("cp.async.wait_group 1;" ::: "memory")
#define CP_WAIT0()  asm volatile("cp.async.wait_group 0;" ::: "memory")

#define MMA_OP(c, a0, a1, a2, a3, b0, b1) \
    asm volatile("mma.sync.aligned.m16n8k16.row.col.f32.f16.f16.f32 " \
        "{%0,%1,%2,%3}, {%4,%5,%6,%7}, {%8,%9}, {%0,%1,%2,%3};" \
        : "+f"((c)[0]), "+f"((c)[1]), "+f"((c)[2]), "+f"((c)[3]) \
        : "r"(a0), "r"(a1), "r"(a2), "r"(a3), "r"(b0), "r"(b1))

// ---------------- double-buffered split-fp16 HMMA GEMM ----------------
// NMMA=3: AhBh + AlBh + AhBl.  NMMA=2: AhBh + AlBh.
template<int BM,int BN,int WM,int WN,int NMMA,bool RELU,bool HASE,bool WF32,bool WSPLIT,bool XIOUT>
__global__ void __launch_bounds__((BM/WM)*(BN/WN)*32, 2)
mgemm2_k(const __half* __restrict__ Ah, const __half* __restrict__ Al,
         size_t sA, int ldA, int zAs,
         const __half* __restrict__ Bh, const __half* __restrict__ Bl,
         size_t sB, int ldB, int zBm,
         const float* __restrict__ bias, int sBias,
         const float* __restrict__ E, size_t sE, int ldE,
         float* __restrict__ C, __half* __restrict__ Ch, __half* __restrict__ Cl,
         size_t sC, int ldC, int K)
{
    constexpr int NWARP = (BM/WM)*(BN/WN);
    constexpr int NT = NWARP * 32;
    constexpr int PAD = 40;
    constexpr int MF = WM / 16, NF = WN / 8;
    constexpr int ABYTES = BM * PAD * 2;
    constexpr int BBYTES = BN * PAD * 2;
    constexpr int STG = 2 * ABYTES + 2 * BBYTES;

    extern __shared__ char dsm[];
    uint32_t smem_base = (uint32_t)__cvta_generic_to_shared(dsm);

    int tid = threadIdx.x, warp = tid >> 5, lane = tid & 31;
    int z = blockIdx.z, m0 = blockIdx.y * BM, n0 = blockIdx.x * BN;

    Ah += (size_t)(z >> zAs) * sA + (size_t)m0 * ldA;
    Al += (size_t)(z >> zAs) * sA + (size_t)m0 * ldA;
    Bh += (size_t)(z & zBm) * sB + (size_t)n0 * ldB;
    Bl += (size_t)(z & zBm) * sB + (size_t)n0 * ldB;

    int wm = warp % (BM / WM), wn = warp / (BM / WM);
    int mB = wm * WM, nB = wn * WN;

    float acc[MF][NF][4];
    #pragma unroll
    for (int i = 0; i < MF; i++)
        #pragma unroll
        for (int j = 0; j < NF; j++)
            #pragma unroll
            for (int q = 0; q < 4; q++) acc[i][j][q] = 0.f;

    const int nk = K / 32;
    auto issue = [&](int kt, int stg) {
        int k0 = kt * 32;
        uint32_t base = smem_base + stg * STG;
        #pragma unroll
        for (int j = 0; j < BM * 4 / NT; j++) {
            int idx = tid + j * NT;
            int row = idx >> 2, c8 = idx & 3;
            uint32_t d = base + (uint32_t)(row * PAD + c8 * 8) * 2;
            cpa16(d, Ah + (size_t)row * ldA + k0 + c8 * 8);
            cpa16(d + ABYTES, Al + (size_t)row * ldA + k0 + c8 * 8);
        }
        #pragma unroll
        for (int j = 0; j < BN * 4 / NT; j++) {
            int idx = tid + j * NT;
            int row = idx >> 2, c8 = idx & 3;
            uint32_t d = base + 2 * ABYTES + (uint32_t)(row * PAD + c8 * 8) * 2;
            cpa16(d, Bh + (size_t)row * ldB + k0 + c8 * 8);
            if (NMMA == 3) cpa16(d + BBYTES, Bl + (size_t)row * ldB + k0 + c8 * 8);
        }
    };

    issue(0, 0);
    CP_COMMIT();

    for (int kt = 0; kt < nk; kt++) {
        int cur = kt & 1;
        if (kt + 1 < nk) {
            issue(kt + 1, cur ^ 1);
            CP_COMMIT();
            CP_WAIT1();
        } else {
            CP_WAIT0();
        }
        __syncthreads();

        const __half* sAh = (const __half*)(dsm + cur * STG);
        const __half* sAl = sAh + BM * PAD;
        const __half* sBh = (const __half*)(dsm + cur * STG + 2 * ABYTES);
        const __half* sBl = sBh + BN * PAD;

        #pragma unroll
        for (int ks = 0; ks < 32; ks += 16) {
            int kk = ks + (lane & 3) * 2;
            int r0 = mB + (lane >> 2);
            uint32_t ah[MF][4], al[MF][4];
            #pragma unroll
            for (int mf = 0; mf < MF; mf++) {
                int r = r0 + mf * 16;
                ah[mf][0] = *reinterpret_cast<const uint32_t*>(&sAh[r * PAD + kk]);
                ah[mf][1] = *reinterpret_cast<const uint32_t*>(&sAh[(r + 8) * PAD + kk]);
                ah[mf][2] = *reinterpret_cast<const uint32_t*>(&sAh[r * PAD + kk + 8]);
                ah[mf][3] = *reinterpret_cast<const uint32_t*>(&sAh[(r + 8) * PAD + kk + 8]);
                al[mf][0] = *reinterpret_cast<const uint32_t*>(&sAl[r * PAD + kk]);
                al[mf][1] = *reinterpret_cast<const uint32_t*>(&sAl[(r + 8) * PAD + kk]);
                al[mf][2] = *reinterpret_cast<const uint32_t*>(&sAl[r * PAD + kk + 8]);
                al[mf][3] = *reinterpret_cast<const uint32_t*>(&sAl[(r + 8) * PAD + kk + 8]);
            }
            #pragma unroll
            for (int nf = 0; nf < NF; nf++) {
                int cB = nB + nf * 8 + (lane >> 2);
                uint32_t bh0 = *reinterpret_cast<const uint32_t*>(&sBh[cB * PAD + kk]);
                uint32_t bh1 = *reinterpret_cast<const uint32_t*>(&sBh[cB * PAD + kk + 8]);
                uint32_t bl0 = 0, bl1 = 0;
                if (NMMA == 3) {
                    bl0 = *reinterpret_cast<const uint32_t*>(&sBl[cB * PAD + kk]);
                    bl1 = *reinterpret_cast<const uint32_t*>(&sBl[cB * PAD + kk + 8]);
                }
                #pragma unroll
                for (int mf = 0; mf < MF; mf++) {
                    MMA_OP(acc[mf][nf], ah[mf][0], ah[mf][1], ah[mf][2], ah[mf][3], bh0, bh1);
                    MMA_OP(acc[mf][nf], al[mf][0], al[mf][1], al[mf][2], al[mf][3], bh0, bh1);
                    if (NMMA == 3)
                        MMA_OP(acc[mf][nf], ah[mf][0], ah[mf][1], ah[mf][2], ah[mf][3], bl0, bl1);
                }
            }
        }
        __syncthreads();
    }

    // ---- epilogue ----
    if (!XIOUT) {
        size_t cb = (size_t)z * sC + (size_t)m0 * ldC + n0;
        if (WF32) C += cb;
        if (WSPLIT) { Ch += cb; Cl += cb; }
    } else {
        Ch += (size_t)z * sC;
        Cl += (size_t)z * sC;
    }
    if (HASE) E += (size_t)z * sE + (size_t)m0 * ldE + n0;

    #pragma unroll
    for (int mf = 0; mf < MF; mf++) {
        #pragma unroll
        for (int nf = 0; nf < NF; nf++) {
            int r = mB + mf * 16 + (lane >> 2);
            int cc = nB + nf * 8 + (lane & 3) * 2;
            float b0 = 0.f, b1 = 0.f;
            if (bias) {
                b0 = bias[(size_t)z * sBias + n0 + cc];
                b1 = bias[(size_t)z * sBias + n0 + cc + 1];
            }
            float v0 = acc[mf][nf][0] + b0, v1 = acc[mf][nf][1] + b1;
            float v2 = acc[mf][nf][2] + b0, v3 = acc[mf][nf][3] + b1;
            if (HASE) {
                v0 += E[(size_t)r * ldE + cc];       v1 += E[(size_t)r * ldE + cc + 1];
                v2 += E[(size_t)(r + 8) * ldE + cc]; v3 += E[(size_t)(r + 8) * ldE + cc + 1];
            }
            if (RELU) {
                v0 = fmaxf(v0, 0.f); v1 = fmaxf(v1, 0.f);
                v2 = fmaxf(v2, 0.f); v3 = fmaxf(v3, 0.f);
            }
            if (WF32 && !XIOUT) {
                *reinterpret_cast<float2*>(&C[(size_t)r * ldC + cc]) = make_float2(v0, v1);
                *reinterpret_cast<float2*>(&C[(size_t)(r + 8) * ldC + cc]) = make_float2(v2, v3);
            }
            if (WSPLIT || XIOUT) {
                __half2 h01 = __float22half2_rn(make_float2(v0, v1));
                float2 hr01 = __half22float2(h01);
                __half2 l01 = __float22half2_rn(make_float2(v0 - hr01.x, v1 - hr01.y));
                __half2 h23 = __float22half2_rn(make_float2(v2, v3));
                float2 hr23 = __half22float2(h23);
                __half2 l23 = __float22half2_rn(make_float2(v2 - hr23.x, v3 - hr23.y));
                if (XIOUT) {
                    int n = n0 + cc;
                    size_t o0 = (size_t)(n >> 5) * (Ln * Cn) + (size_t)(m0 + r) * Cn + (n & 31);
                    size_t o2 = o0 + 8 * Cn;
                    *reinterpret_cast<__half2*>(&Ch[o0]) = h01;
                    *reinterpret_cast<__half2*>(&Cl[o0]) = l01;
                    *reinterpret_cast<__half2*>(&Ch[o2]) = h23;
                    *reinterpret_cast<__half2*>(&Cl[o2]) = l23;
                } else {
                    *reinterpret_cast<__half2*>(&Ch[(size_t)r * ldC + cc]) = h01;
                    *reinterpret_cast<__half2*>(&Cl[(size_t)r * ldC + cc]) = l01;
                    *reinterpret_cast<__half2*>(&Ch[(size_t)(r + 8) * ldC + cc]) = h23;
                    *reinterpret_cast<__half2*>(&Cl[(size_t)(r + 8) * ldC + cc]) = l23;
                }
            }
        }
    }
}

// ---------------- LayerNorm over D (hi/lo in-place) ----------------
__global__ void ln_k(const float* __restrict__ g, const float* __restrict__ bb) {
    int row = blockIdx.x;
    int nb = row >> 10;
    __half* ph = g_predsh + (size_t)row * Dn;
    __half* pl = g_predsl + (size_t)row * Dn;
    int tid = threadIdx.x;
    float v[4];
    float s = 0.f, sq = 0.f;
    #pragma unroll
    for (int j = 0; j < 4; j++) {
        int d = tid + j * 128;
        v[j] = __half2float(ph[d]) + __half2float(pl[d]);
        s += v[j]; sq += v[j] * v[j];
    }
    #pragma unroll
    for (int off = 16; off > 0; off >>= 1) {
        s  += __shfl_xor_sync(0xffffffffu, s, off);
        sq += __shfl_xor_sync(0xffffffffu, sq, off);
    }
    __shared__ float rs[4], rq[4];
    if ((tid & 31) == 0) { rs[tid >> 5] = s; rq[tid >> 5] = sq; }
    __syncthreads();
    s = rs[0] + rs[1] + rs[2] + rs[3];
    sq = rq[0] + rq[1] + rq[2] + rq[3];
    float mean = s * (1.f / 512.f);
    float var = sq * (1.f / 512.f) - mean * mean;
    float rstd = rsqrtf(var + 1e-5f);
    #pragma unroll
    for (int j = 0; j < 4; j++) {
        int d = tid + j * 128;
        float o = (v[j] - mean) * rstd * g[nb * Dn + d] + bb[nb * Dn + d];
        __half h = __float2half(o);
        ph[d] = h;
        pl[d] = __float2half(o - __half2float(h));
    }
}

// ---------------- final: sum blocks, de-normalize ----------------
__global__ void final_k(float* __restrict__ out) {
    size_t i = (size_t)blockIdx.x * 256 + threadIdx.x;
    const size_t TOT = (size_t)Bn * STEPn * SEGn * Cn;
    if (i >= TOT) return;
    int b = (int)(i >> 13);
    int c = (int)(i & 31);
    float a = g_dec2[i] + g_dec2[i + TOT] + g_dec2[i + 2 * TOT] + g_dec2[i + 3 * TOT];
    out[i] = a * g_std[b * Cn + c] + g_mean[b * Cn + c];
}

// ---------------- host ----------------
static inline void* symp(const void* s) { void* p; cudaGetSymbolAddress(&p, s); return p; }

extern "C" void kernel_launch(void* const* d_in, const int* in_sizes, int n_in,
                              void* d_out, int out_size) {
    const float* x_enc = (const float*)d_in[0];
    const float* mw  = (const float*)d_in[4];
    const float* ew1 = (const float*)d_in[5];
    const float* eb1 = (const float*)d_in[6];
    const float* ew2 = (const float*)d_in[7];
    const float* eb2 = (const float*)d_in[8];
    const float* wxh = (const float*)d_in[9];
    const float* whh = (const float*)d_in[10];
    const float* lng = (const float*)d_in[11];
    const float* lnb = (const float*)d_in[12];
    const float* dw1 = (const float*)d_in[13];
    const float* db1 = (const float*)d_in[14];
    const float* dw2 = (const float*)d_in[15];
    const float* db2 = (const float*)d_in[16];
    float* out = (float*)d_out;

    float* p_encx = (float*)symp(g_encx);
    float* p_U32  = (float*)symp(g_U32);
    float* p_dec2 = (float*)symp(g_dec2);
    typedef __half hf;
#define SYM2(nm) hf* p_##nm##h = (hf*)symp(g_##nm##h); hf* p_##nm##l = (hf*)symp(g_##nm##l)
    SYM2(T16); SYM2(xnT); SYM2(xi); SYM2(enc1); SYM2(enc2); SYM2(encx16);
    SYM2(U); SYM2(hA); SYM2(hB); SYM2(preds); SYM2(dec1);
    SYM2(ew1); SYM2(ew2); SYM2(wxh); SYM2(whhT); SYM2(pw); SYM2(dw1); SYM2(dw2);

    const size_t DD = (size_t)Dn * Dn;
    const int SMEMB = 2 * (2 * 128 * 40 * 2 + 2 * 128 * 40 * 2);  // 81920
    auto* fXI2 = mgemm2_k<128,128,64,32,2,false,false,false,true,true>;
    auto* fRS2 = mgemm2_k<128,128,64,32,2,true, false,false,true,false>;
    auto* fS3  = mgemm2_k<128,128,64,32,3,false,false,false,true,false>;
    auto* fFS3 = mgemm2_k<128,128,64,32,3,false,false,true, true,false>;
    auto* fUE3 = mgemm2_k<128,128,64,32,3,false,true, true, true,false>;
    auto* fES3 = mgemm2_k<128,128,64,32,3,false,true, false,true,false>;
    auto* fF2  = mgemm2_k<128,128,64,32,2,false,false,true, false,false>;
    cudaFuncSetAttribute((const void*)fXI2, cudaFuncAttributeMaxDynamicSharedMemorySize, SMEMB);
    cudaFuncSetAttribute((const void*)fRS2, cudaFuncAttributeMaxDynamicSharedMemorySize, SMEMB);
    cudaFuncSetAttribute((const void*)fS3,  cudaFuncAttributeMaxDynamicSharedMemorySize, SMEMB);
    cudaFuncSetAttribute((const void*)fFS3, cudaFuncAttributeMaxDynamicSharedMemorySize, SMEMB);
    cudaFuncSetAttribute((const void*)fUE3, cudaFuncAttributeMaxDynamicSharedMemorySize, SMEMB);
    cudaFuncSetAttribute((const void*)fES3, cudaFuncAttributeMaxDynamicSharedMemorySize, SMEMB);
    cudaFuncSetAttribute((const void*)fF2,  cudaFuncAttributeMaxDynamicSharedMemorySize, SMEMB);

    // ---- prep ----
    cf_k    <<<5, 256>>>(mw);
    rho_k   <<<NBn, 512>>>();
    tbuild_k<<<4096, 256>>>();
    instnorm_k<<<Bn, 256>>>(x_enc);

    split_k<<<(NBn*Hn*FINn+255)/256,256>>>(ew1, p_ew1h, p_ew1l, NBn*Hn*FINn);
    split_k<<<(NBn*Dn*Hn +255)/256,256>>>(ew2, p_ew2h, p_ew2l, NBn*Dn*Hn);
    split_k<<<(NBn*Dn*Dn +255)/256,256>>>(wxh, p_wxhh, p_wxhl, NBn*Dn*Dn);
    split_k<<<(NBn*Hn*Dn +255)/256,256>>>(dw1, p_dw1h, p_dw1l, NBn*Hn*Dn);
    split_k<<<(NBn*FINn*Hn+255)/256,256>>>(dw2, p_dw2h, p_dw2l, NBn*FINn*Hn);
    splitcp_k<<<(NBn*Dn*Dn+255)/256, 256>>>(whh);                 // pw slot 0 = Whh
    tsplit_k<<<dim3(Dn/32, Dn/32, NBn), 256>>>(whh, p_whhTh, p_whhTl, Dn, Dn);

    // ---- Whh powers: pw slots 1..3 = Whh^2, Whh^3, Whh^4 (C = A @ whhT^T = A @ Whh) ----
    for (int pw = 1; pw <= 3; pw++) {
        fS3<<<dim3(Dn/128, Dn/128, NBn), 256, SMEMB>>>(
            p_pwh + (pw-1)*DD, p_pwl + (pw-1)*DD, 4*DD, Dn, 0,
            p_whhTh, p_whhTl, DD, Dn, 0x7fffffff,
            nullptr, 0, nullptr, 0, 0,
            nullptr, p_pwh + pw*DD, p_pwl + pw*DD, 4*DD, Dn, Dn);
    }

    // ---- irfft: xi[nb] = T16[nb] @ xnT^T  (2-MMA) ----
    fXI2<<<dim3((Bn*Cn)/128, Ln/128, NBn), 256, SMEMB>>>(
        p_T16h, p_T16l, (size_t)Ln*Ln, Ln, 0,
        p_xnTh, p_xnTl, 0, Ln, 0,
        nullptr, 0, nullptr, 0, 0,
        nullptr, p_xih, p_xil, (size_t)Bn*Ln*Cn, Cn, Ln);

    // ---- enc L1: relu(xi @ ew1^T + eb1)  (2-MMA) ----
    fRS2<<<dim3(Hn/128, (Bn*FREQn)/128, NBn), 256, SMEMB>>>(
        p_xih, p_xil, (size_t)Bn*Ln*Cn, FINn, 0,
        p_ew1h, p_ew1l, (size_t)Hn*FINn, FINn, 0x7fffffff,
        eb1, Hn, nullptr, 0, 0,
        nullptr, p_enc1h, p_enc1l, (size_t)Bn*FREQn*Hn, Hn, FINn);

    // ---- enc L2 (3-MMA) ----
    fS3<<<dim3(Dn/128, (Bn*FREQn)/128, NBn), 256, SMEMB>>>(
        p_enc1h, p_enc1l, (size_t)Bn*FREQn*Hn, Hn, 0,
        p_ew2h, p_ew2l, (size_t)Dn*Hn, Hn, 0x7fffffff,
        eb2, Dn, nullptr, 0, 0,
        nullptr, p_enc2h, p_enc2l, (size_t)Bn*FREQn*Dn, Dn, Hn);

    // ---- encx = enc @ Wxh^T (3-MMA; fp32 + split out) ----
    fFS3<<<dim3(Dn/128, (Bn*FREQn)/128, NBn), 256, SMEMB>>>(
        p_enc2h, p_enc2l, (size_t)Bn*FREQn*Dn, Dn, 0,
        p_wxhh, p_wxhl, (size_t)Dn*Dn, Dn, 0x7fffffff,
        nullptr, 0, nullptr, 0, 0,
        p_encx, p_encx16h, p_encx16l, (size_t)Bn*FREQn*Dn, Dn, Dn);

    // ---- U_t = encx_t + encx_{t-1} @ Whh^T for t in {1,3,5,7}  (one launch) ----
    fUE3<<<dim3(Dn/128, (Bn*4)/128, NBn), 256, SMEMB>>>(
        p_encx16h, p_encx16l, (size_t)Bn*FREQn*Dn, 2*Dn, 0,
        p_pwh, p_pwl, 4*DD, Dn, 0x7fffffff,
        nullptr, 0,
        p_encx + Dn, (size_t)Bn*FREQn*Dn, 2*Dn,
        p_U32, p_Uh, p_Ul, (size_t)Bn*4*Dn, Dn, Dn);

    // ---- stride-2 chain: h_{t+2} = U_{t+2} + h_t @ (Whh^2)^T ----
    // h3:
    fES3<<<dim3(Dn/128, Bn/128, NBn), 256, SMEMB>>>(
        p_Uh, p_Ul, (size_t)Bn*4*Dn, 4*Dn, 0,
        p_pwh + DD, p_pwl + DD, 4*DD, Dn, 0x7fffffff,
        nullptr, 0,
        p_U32 + Dn, (size_t)Bn*4*Dn, 4*Dn,
        nullptr, p_hAh, p_hAl, (size_t)Bn*Dn, Dn, Dn);
    // h5:
    fES3<<<dim3(Dn/128, Bn/128, NBn), 256, SMEMB>>>(
        p_hAh, p_hAl, (size_t)Bn*Dn, Dn, 0,
        p_pwh + DD, p_pwl + DD, 4*DD, Dn, 0x7fffffff,
        nullptr, 0,
        p_U32 + 2*Dn, (size_t)Bn*4*Dn, 4*Dn,
        nullptr, p_hBh, p_hBl, (size_t)Bn*Dn, Dn, Dn);
    // h7:
    fES3<<<dim3(Dn/128, Bn/128, NBn), 256, SMEMB>>>(
        p_hBh, p_hBl, (size_t)Bn*Dn, Dn, 0,
        p_pwh + DD, p_pwl + DD, 4*DD, Dn, 0x7fffffff,
        nullptr, 0,
        p_U32 + 3*Dn, (size_t)Bn*4*Dn, 4*Dn,
        nullptr, p_hAh, p_hAl, (size_t)Bn*Dn, Dn, Dn);

    // ---- free-run: preds = h7 @ [Whh;Whh^2;Whh^3;Whh^4]^T  (one launch) ----
    fS3<<<dim3((4*Dn)/128, Bn/128, NBn), 256, SMEMB>>>(
        p_hAh, p_hAl, (size_t)Bn*Dn, Dn, 0,
        p_pwh, p_pwl, 4*DD, Dn, 0x7fffffff,
        nullptr, 0, nullptr, 0, 0,
        nullptr, p_predsh, p_predsl, (size_t)Bn*STEPn*Dn, STEPn*Dn, Dn);

    ln_k<<<NBn*Bn*STEPn, 128>>>(lng, lnb);

    // ---- dec L1: relu(preds @ dw1^T + db1)  (2-MMA) ----
    fRS2<<<dim3(Hn/128, (Bn*STEPn)/128, NBn), 256, SMEMB>>>(
        p_predsh, p_predsl, (size_t)Bn*STEPn*Dn, Dn, 0,
        p_dw1h, p_dw1l, (size_t)Hn*Dn, Dn, 0x7fffffff,
        db1, Hn, nullptr, 0, 0,
        nullptr, p_dec1h, p_dec1l, (size_t)Bn*STEPn*Hn, Hn, Dn);

    // ---- dec L2 (2-MMA; fp32 out) ----
    fF2<<<dim3(FINn/128, (Bn*STEPn)/128, NBn), 256, SMEMB>>>(
        p_dec1h, p_dec1l, (size_t)Bn*STEPn*Hn, Hn, 0,
        p_dw2h, p_dw2l, (size_t)FINn*Hn, Hn, 0x7fffffff,
        db2, FINn, nullptr, 0, 0,
        p_dec2, nullptr, nullptr, (size_t)Bn*STEPn*FINn, FINn, Hn);

    final_k<<<(Bn*STEPn*SEGn*Cn + 255)/256, 256>>>(out);
}